// round 1
// baseline (speedup 1.0000x reference)
#include <cuda_runtime.h>
#include <cuda_bf16.h>

// Problem constants: x [1, 4096, 1024], 16 heads, dh = 64.
#define S 4096
#define D 1024
#define H 16
#define DH 64

// Scratch (device globals — no runtime allocation allowed).
__device__ float g_Q[S * D];
__device__ float g_K[S * D];
__device__ float g_V[S * D];
__device__ float g_A[S * D];   // attention output (pre output-projection)

// ---------------------------------------------------------------------------
// Tiled fp32 GEMM core: C[m,n] = sum_k A[m,k] * B[n,k]
// A: [M x K] row-major, B: [N x K] row-major (nn.Linear weight layout),
// so this computes X @ W^T directly. Block tile 128x128, K-step 8,
// 256 threads, 8x8 accumulators per thread.
// ---------------------------------------------------------------------------
#define BM 128
#define BN 128
#define BK 8

__device__ __forceinline__ void sgemm_tile_tn(
    const float* __restrict__ A, const float* __restrict__ B,
    float* __restrict__ C, int M, int N, int K, int bm, int bn)
{
    __shared__ float As[BK][BM];
    __shared__ float Bs[BK][BN];

    const int tid = threadIdx.x;       // 0..255
    const int tx = tid & 15;           // 0..15
    const int ty = tid >> 4;           // 0..15

    // Global-load mapping: 256 threads each load one float4 from A and B
    // per K-step (128 rows x 8 cols = 1024 floats = 256 float4).
    const int lrow = tid >> 1;         // 0..127
    const int lcol = (tid & 1) * 4;    // 0 or 4

    const float* Aptr = A + (size_t)(bm + lrow) * K + lcol;
    const float* Bptr = B + (size_t)(bn + lrow) * K + lcol;

    float acc[8][8];
#pragma unroll
    for (int i = 0; i < 8; i++)
#pragma unroll
        for (int j = 0; j < 8; j++) acc[i][j] = 0.0f;

    for (int k0 = 0; k0 < K; k0 += BK) {
        float4 av = *(const float4*)(Aptr + k0);
        float4 bv = *(const float4*)(Bptr + k0);

        __syncthreads();   // previous iteration's reads are done
        As[lcol + 0][lrow] = av.x;
        As[lcol + 1][lrow] = av.y;
        As[lcol + 2][lrow] = av.z;
        As[lcol + 3][lrow] = av.w;
        Bs[lcol + 0][lrow] = bv.x;
        Bs[lcol + 1][lrow] = bv.y;
        Bs[lcol + 2][lrow] = bv.z;
        Bs[lcol + 3][lrow] = bv.w;
        __syncthreads();

#pragma unroll
        for (int k = 0; k < BK; k++) {
            float4 a0 = *(const float4*)&As[k][ty * 8];
            float4 a1 = *(const float4*)&As[k][ty * 8 + 4];
            float4 b0 = *(const float4*)&Bs[k][tx * 8];
            float4 b1 = *(const float4*)&Bs[k][tx * 8 + 4];
            float a[8] = {a0.x, a0.y, a0.z, a0.w, a1.x, a1.y, a1.z, a1.w};
            float b[8] = {b0.x, b0.y, b0.z, b0.w, b1.x, b1.y, b1.z, b1.w};
#pragma unroll
            for (int i = 0; i < 8; i++)
#pragma unroll
                for (int j = 0; j < 8; j++)
                    acc[i][j] = fmaf(a[i], b[j], acc[i][j]);
        }
    }

#pragma unroll
    for (int i = 0; i < 8; i++) {
        float* Crow = C + (size_t)(bm + ty * 8 + i) * N + bn + tx * 8;
        float4 c0 = {acc[i][0], acc[i][1], acc[i][2], acc[i][3]};
        float4 c1 = {acc[i][4], acc[i][5], acc[i][6], acc[i][7]};
        *(float4*)(Crow) = c0;
        *(float4*)(Crow + 4) = c1;
    }
}

// QKV projection: grid.z selects which weight/output.
__global__ __launch_bounds__(256)
void qkv_gemm_kernel(const float* __restrict__ x,
                     const float* __restrict__ WQ,
                     const float* __restrict__ WK,
                     const float* __restrict__ WV)
{
    const int bn = blockIdx.x * BN;
    const int bm = blockIdx.y * BM;
    const int z = blockIdx.z;
    const float* B = (z == 0) ? WQ : (z == 1) ? WK : WV;
    float* C = (z == 0) ? g_Q : (z == 1) ? g_K : g_V;
    sgemm_tile_tn(x, B, C, S, D, D, bm, bn);
}

// Output projection: d_out = g_A @ W_O^T
__global__ __launch_bounds__(256)
void out_gemm_kernel(const float* __restrict__ WO, float* __restrict__ out)
{
    const int bn = blockIdx.x * BN;
    const int bm = blockIdx.y * BM;
    sgemm_tile_tn(g_A, WO, out, S, D, D, bm, bn);
}

// ---------------------------------------------------------------------------
// Flash attention: one thread per query row, online softmax.
// Block = 128 threads = 128 query rows; K/V staged in 64-row SMEM tiles.
// Scale 1/sqrt(64) = 0.125 folded into q.
// ---------------------------------------------------------------------------
#define TK 64   // keys per tile

__global__ __launch_bounds__(128)
void flash_attn_kernel()
{
    const int h = blockIdx.y;
    const int qr = blockIdx.x * 128 + threadIdx.x;  // query row 0..4095

    __shared__ float Ks[TK][DH];
    __shared__ float Vs[TK][DH];

    float q[DH], o[DH];
    const float* Qp = g_Q + (size_t)qr * D + h * DH;
#pragma unroll
    for (int k = 0; k < DH; k++) {
        q[k] = Qp[k] * 0.125f;
        o[k] = 0.0f;
    }

    float m = -1e30f;
    float l = 0.0f;

    for (int t = 0; t < S / TK; t++) {
        const int base = t * TK;
        __syncthreads();  // previous tile reads complete
        // Load K/V tile: 64 rows x 64 cols = 1024 float4 per matrix,
        // 128 threads -> 8 float4 each.
        for (int idx = threadIdx.x; idx < TK * (DH / 4); idx += 128) {
            const int row = idx >> 4;
            const int c = (idx & 15) * 4;
            const size_t goff = (size_t)(base + row) * D + h * DH + c;
            *(float4*)&Ks[row][c] = *(const float4*)&g_K[goff];
            *(float4*)&Vs[row][c] = *(const float4*)&g_V[goff];
        }
        __syncthreads();

#pragma unroll 1
        for (int j = 0; j < TK; j++) {
            float s0 = 0.f, s1 = 0.f, s2 = 0.f, s3 = 0.f;
#pragma unroll
            for (int k = 0; k < DH; k += 4) {
                s0 = fmaf(q[k + 0], Ks[j][k + 0], s0);
                s1 = fmaf(q[k + 1], Ks[j][k + 1], s1);
                s2 = fmaf(q[k + 2], Ks[j][k + 2], s2);
                s3 = fmaf(q[k + 3], Ks[j][k + 3], s3);
            }
            const float s = (s0 + s1) + (s2 + s3);
            if (s > m) {
                const float corr = __expf(m - s);
                l *= corr;
#pragma unroll
                for (int k = 0; k < DH; k++) o[k] *= corr;
                m = s;
            }
            const float p = __expf(s - m);
            l += p;
#pragma unroll
            for (int k = 0; k < DH; k++)
                o[k] = fmaf(p, Vs[j][k], o[k]);
        }
    }

    const float inv = 1.0f / l;
    float* Op = g_A + (size_t)qr * D + h * DH;
#pragma unroll
    for (int k = 0; k < DH; k++) Op[k] = o[k] * inv;
}

// ---------------------------------------------------------------------------
// kernel_launch
// Inputs: d_in[0]=x [1,4096,1024], d_in[1..4]=W_Q,W_K,W_V,W_O [1024,1024]
// Output: [1,4096,1024] fp32
// ---------------------------------------------------------------------------
extern "C" void kernel_launch(void* const* d_in, const int* in_sizes, int n_in,
                              void* d_out, int out_size)
{
    const float* x  = (const float*)d_in[0];
    const float* WQ = (const float*)d_in[1];
    const float* WK = (const float*)d_in[2];
    const float* WV = (const float*)d_in[3];
    const float* WO = (const float*)d_in[4];
    float* out = (float*)d_out;

    dim3 gq(D / BN, S / BM, 3);       // (8, 32, 3)
    qkv_gemm_kernel<<<gq, 256>>>(x, WQ, WK, WV);

    dim3 ga(S / 128, H);              // (32, 16)
    flash_attn_kernel<<<ga, 128>>>();

    dim3 go(D / BN, S / BM);          // (8, 32)
    out_gemm_kernel<<<go, 256>>>(WO, out);
}

// round 2
// speedup vs baseline: 3.3091x; 3.3091x over previous
#include <cuda_runtime.h>
#include <cuda_bf16.h>

#define S 4096
#define D 1024
#define H 16

// ---------------------------------------------------------------------------
// Device-global scratch (no runtime allocation allowed).
// All fp32 tensors are stored as split bf16 pairs (hi + lo) so that
// 3x bf16 MMA (hi*hi + hi*lo + lo*hi) recovers ~17 mantissa bits.
// ---------------------------------------------------------------------------
__device__ __nv_bfloat16 g_xh[S * D], g_xl[S * D];
__device__ __nv_bfloat16 g_wh[3][D * D], g_wl[3][D * D];
__device__ __nv_bfloat16 g_woh[D * D], g_wol[D * D];
__device__ __nv_bfloat16 g_qh[S * D], g_ql[S * D];
__device__ __nv_bfloat16 g_kh[S * D], g_kl[S * D];
__device__ __nv_bfloat16 g_vh[S * D], g_vl[S * D];
__device__ __nv_bfloat16 g_ah[S * D], g_al[S * D];

// ---------------------------------------------------------------------------
// Helpers
// ---------------------------------------------------------------------------
__device__ __forceinline__ unsigned smem_u32(const void* p) {
    return (unsigned)__cvta_generic_to_shared(p);
}

__device__ __forceinline__ void split_pair(float f0, float f1,
                                           unsigned& h, unsigned& l) {
    __nv_bfloat162 hh = __floats2bfloat162_rn(f0, f1);
    float r0 = f0 - __bfloat162float(hh.x);
    float r1 = f1 - __bfloat162float(hh.y);
    __nv_bfloat162 ll = __floats2bfloat162_rn(r0, r1);
    h = *reinterpret_cast<unsigned*>(&hh);
    l = *reinterpret_cast<unsigned*>(&ll);
}

__device__ __forceinline__ void ldm_x4(unsigned addr, unsigned& r0, unsigned& r1,
                                       unsigned& r2, unsigned& r3) {
    asm volatile("ldmatrix.sync.aligned.m8n8.x4.shared.b16 {%0,%1,%2,%3},[%4];\n"
                 : "=r"(r0), "=r"(r1), "=r"(r2), "=r"(r3) : "r"(addr));
}

__device__ __forceinline__ void ldm_x4_t(unsigned addr, unsigned& r0, unsigned& r1,
                                         unsigned& r2, unsigned& r3) {
    asm volatile("ldmatrix.sync.aligned.m8n8.x4.trans.shared.b16 {%0,%1,%2,%3},[%4];\n"
                 : "=r"(r0), "=r"(r1), "=r"(r2), "=r"(r3) : "r"(addr));
}

__device__ __forceinline__ void mma_bf16(float c[4], const unsigned a[4],
                                         const unsigned b[2]) {
    asm volatile(
        "mma.sync.aligned.m16n8k16.row.col.f32.bf16.bf16.f32 "
        "{%0,%1,%2,%3},{%4,%5,%6,%7},{%8,%9},{%0,%1,%2,%3};\n"
        : "+f"(c[0]), "+f"(c[1]), "+f"(c[2]), "+f"(c[3])
        : "r"(a[0]), "r"(a[1]), "r"(a[2]), "r"(a[3]), "r"(b[0]), "r"(b[1]));
}

// ---------------------------------------------------------------------------
// Conversion kernels: fp32 -> (bf16 hi, bf16 lo)
// ---------------------------------------------------------------------------
__global__ __launch_bounds__(256) void conv_x_kernel(const float* __restrict__ x) {
    int i = (blockIdx.x * 256 + threadIdx.x) * 4;
    float4 v = *(const float4*)(x + i);
    unsigned h0, l0, h1, l1;
    split_pair(v.x, v.y, h0, l0);
    split_pair(v.z, v.w, h1, l1);
    unsigned* ph = (unsigned*)g_xh;
    unsigned* pl = (unsigned*)g_xl;
    ph[(i >> 1) + 0] = h0; ph[(i >> 1) + 1] = h1;
    pl[(i >> 1) + 0] = l0; pl[(i >> 1) + 1] = l1;
}

__global__ __launch_bounds__(256) void conv_w_kernel(const float* __restrict__ WQ,
                                                     const float* __restrict__ WK,
                                                     const float* __restrict__ WV,
                                                     const float* __restrict__ WO) {
    int i = (blockIdx.x * 256 + threadIdx.x) * 4;
    int m = i >> 20;                 // which matrix (D*D = 2^20)
    int off = i & ((D * D) - 1);
    const float* W = (m == 0) ? WQ : (m == 1) ? WK : (m == 2) ? WV : WO;
    __nv_bfloat16* dh = (m == 3) ? g_woh : g_wh[m];
    __nv_bfloat16* dl = (m == 3) ? g_wol : g_wl[m];
    float4 v = *(const float4*)(W + off);
    unsigned h0, l0, h1, l1;
    split_pair(v.x, v.y, h0, l0);
    split_pair(v.z, v.w, h1, l1);
    ((unsigned*)dh)[(off >> 1) + 0] = h0; ((unsigned*)dh)[(off >> 1) + 1] = h1;
    ((unsigned*)dl)[(off >> 1) + 0] = l0; ((unsigned*)dl)[(off >> 1) + 1] = l1;
}

// ---------------------------------------------------------------------------
// GEMM core: C[128x128] = A[128xK] * B[128xK]^T   (both K-contiguous),
// split-bf16 x3 MMA. 256 threads = 8 warps in 2(m) x 4(n); warp tile 64x32.
// SMEM tiles 128x32 bf16, XOR-swizzled for conflict-free ldmatrix.
// ---------------------------------------------------------------------------
__device__ __forceinline__ void gemm_core(const __nv_bfloat16* __restrict__ Ah,
                                          const __nv_bfloat16* __restrict__ Al,
                                          const __nv_bfloat16* __restrict__ Bh,
                                          const __nv_bfloat16* __restrict__ Bl,
                                          int bm, int bn, float (&c)[4][4][4]) {
    __shared__ uint4 sm[2048];   // 4 tiles x 512 chunks (8 KB each) = 32 KB

    const int tid = threadIdx.x;
    const int wid = tid >> 5, lane = tid & 31;
    const int wm = wid & 1, wn = wid >> 1;

#pragma unroll
    for (int mt = 0; mt < 4; mt++)
#pragma unroll
        for (int nt = 0; nt < 4; nt++)
#pragma unroll
            for (int j = 0; j < 4; j++) c[mt][nt][j] = 0.0f;

    // global staging: 2 chunks per tile per thread
    const int r0 = tid >> 2, c0 = tid & 3;
    const int r1 = (tid + 256) >> 2;
    const int sw0 = r0 * 4 + (c0 ^ ((r0 >> 1) & 3));
    const int sw1 = r1 * 4 + (c0 ^ ((r1 >> 1) & 3));

    const uint4* gAh0 = (const uint4*)(Ah + (size_t)(bm + r0) * D + c0 * 8);
    const uint4* gAh1 = (const uint4*)(Ah + (size_t)(bm + r1) * D + c0 * 8);
    const uint4* gAl0 = (const uint4*)(Al + (size_t)(bm + r0) * D + c0 * 8);
    const uint4* gAl1 = (const uint4*)(Al + (size_t)(bm + r1) * D + c0 * 8);
    const uint4* gBh0 = (const uint4*)(Bh + (size_t)(bn + r0) * D + c0 * 8);
    const uint4* gBh1 = (const uint4*)(Bh + (size_t)(bn + r1) * D + c0 * 8);
    const uint4* gBl0 = (const uint4*)(Bl + (size_t)(bn + r0) * D + c0 * 8);
    const uint4* gBl1 = (const uint4*)(Bl + (size_t)(bn + r1) * D + c0 * 8);

    const unsigned sb = smem_u32(sm);
    const int lr = (lane & 7) + ((lane >> 3) & 1) * 8;
    const int lc = lane >> 4;

    for (int k0 = 0; k0 < D; k0 += 32) {
        __syncthreads();
        sm[sw0] = *gAh0;        sm[sw1] = *gAh1;
        sm[512 + sw0] = *gAl0;  sm[512 + sw1] = *gAl1;
        sm[1024 + sw0] = *gBh0; sm[1024 + sw1] = *gBh1;
        sm[1536 + sw0] = *gBl0; sm[1536 + sw1] = *gBl1;
        gAh0 += 4; gAh1 += 4; gAl0 += 4; gAl1 += 4;
        gBh0 += 4; gBh1 += 4; gBl0 += 4; gBl1 += 4;
        __syncthreads();

#pragma unroll
        for (int kk = 0; kk < 2; kk++) {
            unsigned ah[4][4], al[4][4], bh[4][2], bl[4][2];
#pragma unroll
            for (int mt = 0; mt < 4; mt++) {
                int row = wm * 64 + mt * 16 + lr;
                int off = (row * 4 + (((kk * 2) + lc) ^ ((row >> 1) & 3))) * 16;
                ldm_x4(sb + off, ah[mt][0], ah[mt][1], ah[mt][2], ah[mt][3]);
                ldm_x4(sb + 8192 + off, al[mt][0], al[mt][1], al[mt][2], al[mt][3]);
            }
#pragma unroll
            for (int np = 0; np < 2; np++) {
                int rown = wn * 32 + np * 16 + lr;
                int off = (rown * 4 + (((kk * 2) + lc) ^ ((rown >> 1) & 3))) * 16;
                unsigned t0, t1, t2, t3;
                ldm_x4(sb + 16384 + off, t0, t1, t2, t3);
                bh[2 * np][0] = t0; bh[2 * np][1] = t2;
                bh[2 * np + 1][0] = t1; bh[2 * np + 1][1] = t3;
                ldm_x4(sb + 24576 + off, t0, t1, t2, t3);
                bl[2 * np][0] = t0; bl[2 * np][1] = t2;
                bl[2 * np + 1][0] = t1; bl[2 * np + 1][1] = t3;
            }
#pragma unroll
            for (int mt = 0; mt < 4; mt++)
#pragma unroll
                for (int nt = 0; nt < 4; nt++) {
                    mma_bf16(c[mt][nt], ah[mt], bh[nt]);
                    mma_bf16(c[mt][nt], ah[mt], bl[nt]);
                    mma_bf16(c[mt][nt], al[mt], bh[nt]);
                }
        }
    }
}

// Projections: Q/K/V = x @ W^T (Q scaled by 1/sqrt(64)); stored as bf16 pairs.
__global__ __launch_bounds__(256) void proj_gemm_kernel() {
    const int z = blockIdx.z;
    const int bm = blockIdx.y * 128, bn = blockIdx.x * 128;
    float c[4][4][4];
    gemm_core(g_xh, g_xl, g_wh[z], g_wl[z], bm, bn, c);

    __nv_bfloat16* Ch = (z == 0) ? g_qh : (z == 1) ? g_kh : g_vh;
    __nv_bfloat16* Cl = (z == 0) ? g_ql : (z == 1) ? g_kl : g_vl;
    const float scale = (z == 0) ? 0.125f : 1.0f;

    const int wid = threadIdx.x >> 5, lane = threadIdx.x & 31;
    const int wm = wid & 1, wn = wid >> 1;
#pragma unroll
    for (int mt = 0; mt < 4; mt++)
#pragma unroll
        for (int nt = 0; nt < 4; nt++) {
            int row = bm + wm * 64 + mt * 16 + (lane >> 2);
            int col = bn + wn * 32 + nt * 8 + (lane & 3) * 2;
            unsigned h, l;
            split_pair(c[mt][nt][0] * scale, c[mt][nt][1] * scale, h, l);
            *(unsigned*)&Ch[(size_t)row * D + col] = h;
            *(unsigned*)&Cl[(size_t)row * D + col] = l;
            split_pair(c[mt][nt][2] * scale, c[mt][nt][3] * scale, h, l);
            *(unsigned*)&Ch[(size_t)(row + 8) * D + col] = h;
            *(unsigned*)&Cl[(size_t)(row + 8) * D + col] = l;
        }
}

// Output projection: out = A @ W_O^T (fp32 result)
__global__ __launch_bounds__(256) void out_gemm_kernel(float* __restrict__ out) {
    const int bm = blockIdx.y * 128, bn = blockIdx.x * 128;
    float c[4][4][4];
    gemm_core(g_ah, g_al, g_woh, g_wol, bm, bn, c);

    const int wid = threadIdx.x >> 5, lane = threadIdx.x & 31;
    const int wm = wid & 1, wn = wid >> 1;
#pragma unroll
    for (int mt = 0; mt < 4; mt++)
#pragma unroll
        for (int nt = 0; nt < 4; nt++) {
            int row = bm + wm * 64 + mt * 16 + (lane >> 2);
            int col = bn + wn * 32 + nt * 8 + (lane & 3) * 2;
            float2 v0 = {c[mt][nt][0], c[mt][nt][1]};
            float2 v1 = {c[mt][nt][2], c[mt][nt][3]};
            *(float2*)&out[(size_t)row * D + col] = v0;
            *(float2*)&out[(size_t)(row + 8) * D + col] = v1;
        }
}

// ---------------------------------------------------------------------------
// Flash attention (FA2-style): block = 128 q rows x 1 head, 8 warps (m16 each).
// Key/value tiles of 64 staged in SMEM; scores/PV via split-bf16 x3 MMA.
// ---------------------------------------------------------------------------
__global__ __launch_bounds__(256) void attn_kernel() {
    __shared__ uint4 sm[2048];   // 32 KB

    const int tid = threadIdx.x, wid = tid >> 5, lane = tid & 31;
    const int h = blockIdx.y;
    const int qb = blockIdx.x * 128;
    const unsigned sb = smem_u32(sm);
    const int lr = (lane & 7) + ((lane >> 3) & 1) * 8;
    const int lc = lane >> 4;

    // ---- stage Q (hi/lo) and load Q fragments into registers ----
#pragma unroll
    for (int t = 0; t < 4; t++) {
        int idx = tid + t * 256;
        int row = idx >> 3, cc = idx & 7;
        int sw = row * 8 + (cc ^ (row & 7));
        size_t g = (size_t)(qb + row) * D + h * 64 + cc * 8;
        sm[sw] = *(const uint4*)&g_qh[g];
        sm[1024 + sw] = *(const uint4*)&g_ql[g];
    }
    __syncthreads();

    unsigned qh[4][4], ql[4][4];
    {
        int row = wid * 16 + lr;
#pragma unroll
        for (int kq = 0; kq < 4; kq++) {
            int off = (row * 8 + (((kq * 2) + lc) ^ (row & 7))) * 16;
            ldm_x4(sb + off, qh[kq][0], qh[kq][1], qh[kq][2], qh[kq][3]);
            ldm_x4(sb + 16384 + off, ql[kq][0], ql[kq][1], ql[kq][2], ql[kq][3]);
        }
    }

    float co[8][4];
#pragma unroll
    for (int nt = 0; nt < 8; nt++)
#pragma unroll
        for (int j = 0; j < 4; j++) co[nt][j] = 0.0f;
    float m0 = -1e30f, m1 = -1e30f, l0 = 0.0f, l1 = 0.0f;

    for (int kt = 0; kt < S / 64; kt++) {
        __syncthreads();
        // stage K/V (hi/lo) tiles: layout Kh[0,512) Kl[512,1024) Vh[1024,1536) Vl[1536,2048)
#pragma unroll
        for (int t = 0; t < 2; t++) {
            int idx = tid + t * 256;
            int row = idx >> 3, cc = idx & 7;
            int sw = row * 8 + (cc ^ (row & 7));
            size_t g = (size_t)(kt * 64 + row) * D + h * 64 + cc * 8;
            sm[sw] = *(const uint4*)&g_kh[g];
            sm[512 + sw] = *(const uint4*)&g_kl[g];
            sm[1024 + sw] = *(const uint4*)&g_vh[g];
            sm[1536 + sw] = *(const uint4*)&g_vl[g];
        }
        __syncthreads();

        // ---- scores: S = Q * K^T (16 x 64 per warp) ----
        float sc[8][4];
#pragma unroll
        for (int nt = 0; nt < 8; nt++)
#pragma unroll
            for (int j = 0; j < 4; j++) sc[nt][j] = 0.0f;

#pragma unroll
        for (int kd = 0; kd < 4; kd++) {
#pragma unroll
            for (int np = 0; np < 4; np++) {
                int rown = np * 16 + lr;
                int off = (rown * 8 + (((kd * 2) + lc) ^ (rown & 7))) * 16;
                unsigned t0, t1, t2, t3, u0, u1, u2, u3;
                ldm_x4(sb + off, t0, t1, t2, t3);            // K hi
                ldm_x4(sb + 8192 + off, u0, u1, u2, u3);     // K lo
                unsigned bh0[2] = {t0, t2}, bh1[2] = {t1, t3};
                unsigned bl0[2] = {u0, u2}, bl1[2] = {u1, u3};
                mma_bf16(sc[2 * np], qh[kd], bh0);
                mma_bf16(sc[2 * np], qh[kd], bl0);
                mma_bf16(sc[2 * np], ql[kd], bh0);
                mma_bf16(sc[2 * np + 1], qh[kd], bh1);
                mma_bf16(sc[2 * np + 1], qh[kd], bl1);
                mma_bf16(sc[2 * np + 1], ql[kd], bh1);
            }
        }

        // ---- online softmax ----
        float tm0 = -1e30f, tm1 = -1e30f;
#pragma unroll
        for (int t = 0; t < 8; t++) {
            tm0 = fmaxf(tm0, fmaxf(sc[t][0], sc[t][1]));
            tm1 = fmaxf(tm1, fmaxf(sc[t][2], sc[t][3]));
        }
        tm0 = fmaxf(tm0, __shfl_xor_sync(0xffffffffu, tm0, 1));
        tm0 = fmaxf(tm0, __shfl_xor_sync(0xffffffffu, tm0, 2));
        tm1 = fmaxf(tm1, __shfl_xor_sync(0xffffffffu, tm1, 1));
        tm1 = fmaxf(tm1, __shfl_xor_sync(0xffffffffu, tm1, 2));
        float mn0 = fmaxf(m0, tm0), mn1 = fmaxf(m1, tm1);
        float corr0 = __expf(m0 - mn0), corr1 = __expf(m1 - mn1);
        m0 = mn0; m1 = mn1;
        float ps0 = 0.0f, ps1 = 0.0f;
#pragma unroll
        for (int t = 0; t < 8; t++) {
            sc[t][0] = __expf(sc[t][0] - m0); ps0 += sc[t][0];
            sc[t][1] = __expf(sc[t][1] - m0); ps0 += sc[t][1];
            sc[t][2] = __expf(sc[t][2] - m1); ps1 += sc[t][2];
            sc[t][3] = __expf(sc[t][3] - m1); ps1 += sc[t][3];
        }
        l0 = l0 * corr0 + ps0;
        l1 = l1 * corr1 + ps1;
#pragma unroll
        for (int nt = 0; nt < 8; nt++) {
            co[nt][0] *= corr0; co[nt][1] *= corr0;
            co[nt][2] *= corr1; co[nt][3] *= corr1;
        }

        // ---- O += P * V ----
#pragma unroll
        for (int u = 0; u < 4; u++) {
            unsigned pah[4], pal[4];
            split_pair(sc[2 * u][0], sc[2 * u][1], pah[0], pal[0]);
            split_pair(sc[2 * u][2], sc[2 * u][3], pah[1], pal[1]);
            split_pair(sc[2 * u + 1][0], sc[2 * u + 1][1], pah[2], pal[2]);
            split_pair(sc[2 * u + 1][2], sc[2 * u + 1][3], pah[3], pal[3]);
#pragma unroll
            for (int jp = 0; jp < 4; jp++) {
                int rowv = u * 16 + lr;
                int off = (rowv * 8 + (((jp * 2) + lc) ^ (rowv & 7))) * 16;
                unsigned t0, t1, t2, t3, u0, u1, u2, u3;
                ldm_x4_t(sb + 16384 + off, t0, t1, t2, t3);   // V hi
                ldm_x4_t(sb + 24576 + off, u0, u1, u2, u3);   // V lo
                unsigned vh0[2] = {t0, t1}, vh1[2] = {t2, t3};
                unsigned vl0[2] = {u0, u1}, vl1[2] = {u2, u3};
                mma_bf16(co[2 * jp], pah, vh0);
                mma_bf16(co[2 * jp], pah, vl0);
                mma_bf16(co[2 * jp], pal, vh0);
                mma_bf16(co[2 * jp + 1], pah, vh1);
                mma_bf16(co[2 * jp + 1], pah, vl1);
                mma_bf16(co[2 * jp + 1], pal, vh1);
            }
        }
    }

    // ---- finalize: normalize and store A as bf16 pair ----
    l0 += __shfl_xor_sync(0xffffffffu, l0, 1);
    l0 += __shfl_xor_sync(0xffffffffu, l0, 2);
    l1 += __shfl_xor_sync(0xffffffffu, l1, 1);
    l1 += __shfl_xor_sync(0xffffffffu, l1, 2);
    float inv0 = 1.0f / l0, inv1 = 1.0f / l1;

    int row = qb + wid * 16 + (lane >> 2);
#pragma unroll
    for (int nt = 0; nt < 8; nt++) {
        int col = h * 64 + nt * 8 + (lane & 3) * 2;
        unsigned hh, ll;
        split_pair(co[nt][0] * inv0, co[nt][1] * inv0, hh, ll);
        *(unsigned*)&g_ah[(size_t)row * D + col] = hh;
        *(unsigned*)&g_al[(size_t)row * D + col] = ll;
        split_pair(co[nt][2] * inv1, co[nt][3] * inv1, hh, ll);
        *(unsigned*)&g_ah[(size_t)(row + 8) * D + col] = hh;
        *(unsigned*)&g_al[(size_t)(row + 8) * D + col] = ll;
    }
}

// ---------------------------------------------------------------------------
// kernel_launch
// ---------------------------------------------------------------------------
extern "C" void kernel_launch(void* const* d_in, const int* in_sizes, int n_in,
                              void* d_out, int out_size) {
    const float* x  = (const float*)d_in[0];
    const float* WQ = (const float*)d_in[1];
    const float* WK = (const float*)d_in[2];
    const float* WV = (const float*)d_in[3];
    const float* WO = (const float*)d_in[4];
    float* out = (float*)d_out;

    conv_x_kernel<<<(S * D) / (256 * 4), 256>>>(x);
    conv_w_kernel<<<(4 * D * D) / (256 * 4), 256>>>(WQ, WK, WV, WO);

    dim3 gq(D / 128, S / 128, 3);
    proj_gemm_kernel<<<gq, 256>>>();

    dim3 ga(S / 128, H);
    attn_kernel<<<ga, 256>>>();

    dim3 go(D / 128, S / 128);
    out_gemm_kernel<<<go, 256>>>(out);
}

// round 3
// speedup vs baseline: 4.0773x; 1.2321x over previous
#include <cuda_runtime.h>
#include <cuda_bf16.h>

#define S 4096
#define D 1024
#define H 16

// ---------------------------------------------------------------------------
// Device-global scratch. All fp32 tensors stored as split bf16 (hi + lo);
// 3x bf16 MMA (hi*hi + hi*lo + lo*hi) recovers ~17 mantissa bits.
// ---------------------------------------------------------------------------
__device__ __nv_bfloat16 g_xh[S * D], g_xl[S * D];
__device__ __nv_bfloat16 g_wh[3][D * D], g_wl[3][D * D];
__device__ __nv_bfloat16 g_woh[D * D], g_wol[D * D];
__device__ __nv_bfloat16 g_qh[S * D], g_ql[S * D];
__device__ __nv_bfloat16 g_kh[S * D], g_kl[S * D];
__device__ __nv_bfloat16 g_vh[S * D], g_vl[S * D];
__device__ __nv_bfloat16 g_ah[S * D], g_al[S * D];

// ---------------------------------------------------------------------------
// Helpers
// ---------------------------------------------------------------------------
__device__ __forceinline__ unsigned smem_u32(const void* p) {
    return (unsigned)__cvta_generic_to_shared(p);
}

__device__ __forceinline__ void split_pair(float f0, float f1,
                                           unsigned& h, unsigned& l) {
    __nv_bfloat162 hh = __floats2bfloat162_rn(f0, f1);
    float r0 = f0 - __bfloat162float(hh.x);
    float r1 = f1 - __bfloat162float(hh.y);
    __nv_bfloat162 ll = __floats2bfloat162_rn(r0, r1);
    h = *reinterpret_cast<unsigned*>(&hh);
    l = *reinterpret_cast<unsigned*>(&ll);
}

__device__ __forceinline__ void ldm_x4(unsigned addr, unsigned& r0, unsigned& r1,
                                       unsigned& r2, unsigned& r3) {
    asm volatile("ldmatrix.sync.aligned.m8n8.x4.shared.b16 {%0,%1,%2,%3},[%4];\n"
                 : "=r"(r0), "=r"(r1), "=r"(r2), "=r"(r3) : "r"(addr));
}

__device__ __forceinline__ void ldm_x4_t(unsigned addr, unsigned& r0, unsigned& r1,
                                         unsigned& r2, unsigned& r3) {
    asm volatile("ldmatrix.sync.aligned.m8n8.x4.trans.shared.b16 {%0,%1,%2,%3},[%4];\n"
                 : "=r"(r0), "=r"(r1), "=r"(r2), "=r"(r3) : "r"(addr));
}

__device__ __forceinline__ void mma_bf16(float c[4], const unsigned a[4],
                                         const unsigned b[2]) {
    asm volatile(
        "mma.sync.aligned.m16n8k16.row.col.f32.bf16.bf16.f32 "
        "{%0,%1,%2,%3},{%4,%5,%6,%7},{%8,%9},{%0,%1,%2,%3};\n"
        : "+f"(c[0]), "+f"(c[1]), "+f"(c[2]), "+f"(c[3])
        : "r"(a[0]), "r"(a[1]), "r"(a[2]), "r"(a[3]), "r"(b[0]), "r"(b[1]));
}

__device__ __forceinline__ void cp16(uint4* dst_smem, const void* src) {
    unsigned d = smem_u32(dst_smem);
    asm volatile("cp.async.cg.shared.global [%0],[%1],16;\n" :: "r"(d), "l"(src));
}
#define CP_COMMIT() asm volatile("cp.async.commit_group;\n" ::: "memory")
#define CP_WAIT1()  asm volatile("cp.async.wait_group 1;\n" ::: "memory")

// ---------------------------------------------------------------------------
// Conversion kernels: fp32 -> (bf16 hi, bf16 lo)
// ---------------------------------------------------------------------------
__global__ __launch_bounds__(256) void conv_x_kernel(const float* __restrict__ x) {
    int i = (blockIdx.x * 256 + threadIdx.x) * 4;
    float4 v = *(const float4*)(x + i);
    unsigned h0, l0, h1, l1;
    split_pair(v.x, v.y, h0, l0);
    split_pair(v.z, v.w, h1, l1);
    ((unsigned*)g_xh)[(i >> 1) + 0] = h0; ((unsigned*)g_xh)[(i >> 1) + 1] = h1;
    ((unsigned*)g_xl)[(i >> 1) + 0] = l0; ((unsigned*)g_xl)[(i >> 1) + 1] = l1;
}

__global__ __launch_bounds__(256) void conv_w_kernel(const float* __restrict__ WQ,
                                                     const float* __restrict__ WK,
                                                     const float* __restrict__ WV,
                                                     const float* __restrict__ WO) {
    int i = (blockIdx.x * 256 + threadIdx.x) * 4;
    int m = i >> 20;
    int off = i & ((D * D) - 1);
    const float* W = (m == 0) ? WQ : (m == 1) ? WK : (m == 2) ? WV : WO;
    __nv_bfloat16* dh = (m == 3) ? g_woh : g_wh[m];
    __nv_bfloat16* dl = (m == 3) ? g_wol : g_wl[m];
    float4 v = *(const float4*)(W + off);
    unsigned h0, l0, h1, l1;
    split_pair(v.x, v.y, h0, l0);
    split_pair(v.z, v.w, h1, l1);
    ((unsigned*)dh)[(off >> 1) + 0] = h0; ((unsigned*)dh)[(off >> 1) + 1] = h1;
    ((unsigned*)dl)[(off >> 1) + 0] = l0; ((unsigned*)dl)[(off >> 1) + 1] = l1;
}

// ---------------------------------------------------------------------------
// GEMM core: C[128x64] = A[128xK] * B[64xK]^T, split-bf16 x3 MMA.
// 256 threads = 8 warps as 4(m) x 2(n); warp tile 32x32.
// K-step 32, cp.async double-buffered (2 x 24KB stages = 48KB).
// Stage layout (uint4 idx): Ah[0,512) Al[512,1024) Bh[1024,1280) Bl[1280,1536)
// ---------------------------------------------------------------------------
__device__ __forceinline__ void gemm_core(const __nv_bfloat16* __restrict__ Ah,
                                          const __nv_bfloat16* __restrict__ Al,
                                          const __nv_bfloat16* __restrict__ Bh,
                                          const __nv_bfloat16* __restrict__ Bl,
                                          int bm, int bn, float (&c)[2][4][4]) {
    __shared__ uint4 sm[3072];   // 48 KB
    const int tid = threadIdx.x;
    const int wid = tid >> 5, lane = tid & 31;
    const int wm = wid >> 1, wn = wid & 1;
    const int lr = (lane & 7) + ((lane >> 3) & 1) * 8;
    const int lc = lane >> 4;
    const unsigned sb = smem_u32(sm);

#pragma unroll
    for (int mt = 0; mt < 2; mt++)
#pragma unroll
        for (int nt = 0; nt < 4; nt++)
#pragma unroll
            for (int j = 0; j < 4; j++) c[mt][nt][j] = 0.0f;

    // per-stage cp.async issue: A 2 hi + 2 lo chunks, B 1 hi + 1 lo per thread
    auto issue = [&](int ks, int s) {
        const int base = s * 1536;
#pragma unroll
        for (int t = 0; t < 2; t++) {
            int q = tid * 2 + t;                 // 0..511
            int r = q >> 2, cc = q & 3;
            int sw = r * 4 + (cc ^ ((r >> 1) & 3));
            size_t g = (size_t)(bm + r) * D + ks * 32 + cc * 8;
            cp16(&sm[base + sw], Ah + g);
            cp16(&sm[base + 512 + sw], Al + g);
        }
        {
            int r = tid >> 2, cc = tid & 3;      // 0..63 rows
            int sw = r * 4 + (cc ^ ((r >> 1) & 3));
            size_t g = (size_t)(bn + r) * D + ks * 32 + cc * 8;
            cp16(&sm[base + 1024 + sw], Bh + g);
            cp16(&sm[base + 1280 + sw], Bl + g);
        }
    };

    issue(0, 0); CP_COMMIT();
    issue(1, 1); CP_COMMIT();

    for (int i = 0; i < D / 32; i++) {
        CP_WAIT1();
        __syncthreads();
        const unsigned base = sb + (i & 1) * 24576;
#pragma unroll
        for (int kk = 0; kk < 2; kk++) {
            unsigned ah[2][4], al[2][4], bh[4][2], bl[4][2];
#pragma unroll
            for (int mt = 0; mt < 2; mt++) {
                int row = wm * 32 + mt * 16 + lr;
                int off = (row * 4 + (((kk * 2) + lc) ^ ((row >> 1) & 3))) * 16;
                ldm_x4(base + off, ah[mt][0], ah[mt][1], ah[mt][2], ah[mt][3]);
                ldm_x4(base + 8192 + off, al[mt][0], al[mt][1], al[mt][2], al[mt][3]);
            }
#pragma unroll
            for (int np = 0; np < 2; np++) {
                int rown = wn * 32 + np * 16 + lr;
                int off = (rown * 4 + (((kk * 2) + lc) ^ ((rown >> 1) & 3))) * 16;
                unsigned t0, t1, t2, t3;
                ldm_x4(base + 16384 + off, t0, t1, t2, t3);
                bh[2 * np][0] = t0; bh[2 * np][1] = t2;
                bh[2 * np + 1][0] = t1; bh[2 * np + 1][1] = t3;
                ldm_x4(base + 20480 + off, t0, t1, t2, t3);
                bl[2 * np][0] = t0; bl[2 * np][1] = t2;
                bl[2 * np + 1][0] = t1; bl[2 * np + 1][1] = t3;
            }
#pragma unroll
            for (int mt = 0; mt < 2; mt++)
#pragma unroll
                for (int nt = 0; nt < 4; nt++) {
                    mma_bf16(c[mt][nt], ah[mt], bh[nt]);
                    mma_bf16(c[mt][nt], ah[mt], bl[nt]);
                    mma_bf16(c[mt][nt], al[mt], bh[nt]);
                }
        }
        __syncthreads();
        if (i + 2 < D / 32) issue(i + 2, i & 1);
        CP_COMMIT();
    }
}

// Projections: Q/K/V = x @ W^T (Q scaled by 1/8); stored as bf16 pairs.
__global__ __launch_bounds__(256) void proj_gemm_kernel() {
    const int z = blockIdx.z;
    const int bm = blockIdx.y * 128, bn = blockIdx.x * 64;
    float c[2][4][4];
    gemm_core(g_xh, g_xl, g_wh[z], g_wl[z], bm, bn, c);

    __nv_bfloat16* Ch = (z == 0) ? g_qh : (z == 1) ? g_kh : g_vh;
    __nv_bfloat16* Cl = (z == 0) ? g_ql : (z == 1) ? g_kl : g_vl;
    const float scale = (z == 0) ? 0.125f : 1.0f;

    const int wid = threadIdx.x >> 5, lane = threadIdx.x & 31;
    const int wm = wid >> 1, wn = wid & 1;
#pragma unroll
    for (int mt = 0; mt < 2; mt++)
#pragma unroll
        for (int nt = 0; nt < 4; nt++) {
            int row = bm + wm * 32 + mt * 16 + (lane >> 2);
            int col = bn + wn * 32 + nt * 8 + (lane & 3) * 2;
            unsigned h, l;
            split_pair(c[mt][nt][0] * scale, c[mt][nt][1] * scale, h, l);
            *(unsigned*)&Ch[(size_t)row * D + col] = h;
            *(unsigned*)&Cl[(size_t)row * D + col] = l;
            split_pair(c[mt][nt][2] * scale, c[mt][nt][3] * scale, h, l);
            *(unsigned*)&Ch[(size_t)(row + 8) * D + col] = h;
            *(unsigned*)&Cl[(size_t)(row + 8) * D + col] = l;
        }
}

// Output projection: out = A @ W_O^T (fp32)
__global__ __launch_bounds__(256) void out_gemm_kernel(float* __restrict__ out) {
    const int bm = blockIdx.y * 128, bn = blockIdx.x * 64;
    float c[2][4][4];
    gemm_core(g_ah, g_al, g_woh, g_wol, bm, bn, c);

    const int wid = threadIdx.x >> 5, lane = threadIdx.x & 31;
    const int wm = wid >> 1, wn = wid & 1;
#pragma unroll
    for (int mt = 0; mt < 2; mt++)
#pragma unroll
        for (int nt = 0; nt < 4; nt++) {
            int row = bm + wm * 32 + mt * 16 + (lane >> 2);
            int col = bn + wn * 32 + nt * 8 + (lane & 3) * 2;
            float2 v0 = {c[mt][nt][0], c[mt][nt][1]};
            float2 v1 = {c[mt][nt][2], c[mt][nt][3]};
            *(float2*)&out[(size_t)row * D + col] = v0;
            *(float2*)&out[(size_t)(row + 8) * D + col] = v1;
        }
}

// ---------------------------------------------------------------------------
// Flash attention: 128-thread CTA = 4 warps = 64 q rows; 32-key tiles,
// cp.async double-buffered (2 x 16KB stages = 32KB smem).
// Stage layout (uint4 idx): Khi[0,256) Klo[256,512) Vhi[512,768) Vlo[768,1024)
// Q fragments loaded directly from gmem into registers.
// ---------------------------------------------------------------------------
__global__ __launch_bounds__(128, 3) void attn_kernel() {
    __shared__ uint4 sm[2048];   // 32 KB

    const int tid = threadIdx.x, wid = tid >> 5, lane = tid & 31;
    const int h = blockIdx.y;
    const int qb = blockIdx.x * 64;
    const unsigned sb = smem_u32(sm);
    const int lr = (lane & 7) + ((lane >> 3) & 1) * 8;
    const int lc = lane >> 4;

    // ---- Q fragments straight from gmem ----
    unsigned qh[4][4], ql[4][4];
    {
        const size_t qoff = (size_t)(qb + wid * 16 + (lane >> 2)) * D + h * 64
                          + (lane & 3) * 2;
#pragma unroll
        for (int kd = 0; kd < 4; kd++) {
            size_t o = qoff + kd * 16;
            qh[kd][0] = *(const unsigned*)&g_qh[o];
            qh[kd][1] = *(const unsigned*)&g_qh[o + 8 * D];
            qh[kd][2] = *(const unsigned*)&g_qh[o + 8];
            qh[kd][3] = *(const unsigned*)&g_qh[o + 8 * D + 8];
            ql[kd][0] = *(const unsigned*)&g_ql[o];
            ql[kd][1] = *(const unsigned*)&g_ql[o + 8 * D];
            ql[kd][2] = *(const unsigned*)&g_ql[o + 8];
            ql[kd][3] = *(const unsigned*)&g_ql[o + 8 * D + 8];
        }
    }

    float co[8][4];
#pragma unroll
    for (int nt = 0; nt < 8; nt++)
#pragma unroll
        for (int j = 0; j < 4; j++) co[nt][j] = 0.0f;
    float m0 = -1e30f, m1 = -1e30f, l0 = 0.0f, l1 = 0.0f;

    auto issue = [&](int kt, int s) {
        const int base = s * 1024;
#pragma unroll
        for (int t = 0; t < 2; t++) {
            int q = tid * 2 + t;                 // 0..255
            int rr = q >> 3, cc = q & 7;
            int sw = rr * 8 + (cc ^ (rr & 7));
            size_t g = (size_t)(kt * 32 + rr) * D + h * 64 + cc * 8;
            cp16(&sm[base + sw], g_kh + g);
            cp16(&sm[base + 256 + sw], g_kl + g);
            cp16(&sm[base + 512 + sw], g_vh + g);
            cp16(&sm[base + 768 + sw], g_vl + g);
        }
    };

    issue(0, 0); CP_COMMIT();
    issue(1, 1); CP_COMMIT();

    for (int kt = 0; kt < S / 32; kt++) {
        CP_WAIT1();
        __syncthreads();
        const unsigned base = sb + (kt & 1) * 16384;

        // ---- scores: 16 x 32 per warp ----
        float sc[4][4];
#pragma unroll
        for (int nt = 0; nt < 4; nt++)
#pragma unroll
            for (int j = 0; j < 4; j++) sc[nt][j] = 0.0f;

#pragma unroll
        for (int kd = 0; kd < 4; kd++) {
#pragma unroll
            for (int np = 0; np < 2; np++) {
                int rown = np * 16 + lr;
                int off = (rown * 8 + (((kd * 2) + lc) ^ (rown & 7))) * 16;
                unsigned t0, t1, t2, t3, u0, u1, u2, u3;
                ldm_x4(base + off, t0, t1, t2, t3);          // K hi
                ldm_x4(base + 4096 + off, u0, u1, u2, u3);   // K lo
                unsigned bh0[2] = {t0, t2}, bh1[2] = {t1, t3};
                unsigned bl0[2] = {u0, u2}, bl1[2] = {u1, u3};
                mma_bf16(sc[2 * np], qh[kd], bh0);
                mma_bf16(sc[2 * np], qh[kd], bl0);
                mma_bf16(sc[2 * np], ql[kd], bh0);
                mma_bf16(sc[2 * np + 1], qh[kd], bh1);
                mma_bf16(sc[2 * np + 1], qh[kd], bl1);
                mma_bf16(sc[2 * np + 1], ql[kd], bh1);
            }
        }

        // ---- online softmax ----
        float tm0 = -1e30f, tm1 = -1e30f;
#pragma unroll
        for (int t = 0; t < 4; t++) {
            tm0 = fmaxf(tm0, fmaxf(sc[t][0], sc[t][1]));
            tm1 = fmaxf(tm1, fmaxf(sc[t][2], sc[t][3]));
        }
        tm0 = fmaxf(tm0, __shfl_xor_sync(0xffffffffu, tm0, 1));
        tm0 = fmaxf(tm0, __shfl_xor_sync(0xffffffffu, tm0, 2));
        tm1 = fmaxf(tm1, __shfl_xor_sync(0xffffffffu, tm1, 1));
        tm1 = fmaxf(tm1, __shfl_xor_sync(0xffffffffu, tm1, 2));
        float mn0 = fmaxf(m0, tm0), mn1 = fmaxf(m1, tm1);
        float corr0 = __expf(m0 - mn0), corr1 = __expf(m1 - mn1);
        m0 = mn0; m1 = mn1;
        float ps0 = 0.0f, ps1 = 0.0f;
#pragma unroll
        for (int t = 0; t < 4; t++) {
            sc[t][0] = __expf(sc[t][0] - m0); ps0 += sc[t][0];
            sc[t][1] = __expf(sc[t][1] - m0); ps0 += sc[t][1];
            sc[t][2] = __expf(sc[t][2] - m1); ps1 += sc[t][2];
            sc[t][3] = __expf(sc[t][3] - m1); ps1 += sc[t][3];
        }
        l0 = l0 * corr0 + ps0;
        l1 = l1 * corr1 + ps1;
#pragma unroll
        for (int nt = 0; nt < 8; nt++) {
            co[nt][0] *= corr0; co[nt][1] *= corr0;
            co[nt][2] *= corr1; co[nt][3] *= corr1;
        }

        // ---- O += P * V ----
#pragma unroll
        for (int u = 0; u < 2; u++) {
            unsigned pah[4], pal[4];
            split_pair(sc[2 * u][0], sc[2 * u][1], pah[0], pal[0]);
            split_pair(sc[2 * u][2], sc[2 * u][3], pah[1], pal[1]);
            split_pair(sc[2 * u + 1][0], sc[2 * u + 1][1], pah[2], pal[2]);
            split_pair(sc[2 * u + 1][2], sc[2 * u + 1][3], pah[3], pal[3]);
#pragma unroll
            for (int jp = 0; jp < 4; jp++) {
                int rowv = u * 16 + lr;
                int off = (rowv * 8 + (((jp * 2) + lc) ^ (rowv & 7))) * 16;
                unsigned t0, t1, t2, t3, u0, u1, u2, u3;
                ldm_x4_t(base + 8192 + off, t0, t1, t2, t3);    // V hi
                ldm_x4_t(base + 12288 + off, u0, u1, u2, u3);   // V lo
                unsigned vh0[2] = {t0, t1}, vh1[2] = {t2, t3};
                unsigned vl0[2] = {u0, u1}, vl1[2] = {u2, u3};
                mma_bf16(co[2 * jp], pah, vh0);
                mma_bf16(co[2 * jp], pah, vl0);
                mma_bf16(co[2 * jp], pal, vh0);
                mma_bf16(co[2 * jp + 1], pah, vh1);
                mma_bf16(co[2 * jp + 1], pah, vl1);
                mma_bf16(co[2 * jp + 1], pal, vh1);
            }
        }
        __syncthreads();
        if (kt + 2 < S / 32) issue(kt + 2, kt & 1);
        CP_COMMIT();
    }

    // ---- finalize ----
    l0 += __shfl_xor_sync(0xffffffffu, l0, 1);
    l0 += __shfl_xor_sync(0xffffffffu, l0, 2);
    l1 += __shfl_xor_sync(0xffffffffu, l1, 1);
    l1 += __shfl_xor_sync(0xffffffffu, l1, 2);
    float inv0 = 1.0f / l0, inv1 = 1.0f / l1;

    int row = qb + wid * 16 + (lane >> 2);
#pragma unroll
    for (int nt = 0; nt < 8; nt++) {
        int col = h * 64 + nt * 8 + (lane & 3) * 2;
        unsigned hh, ll;
        split_pair(co[nt][0] * inv0, co[nt][1] * inv0, hh, ll);
        *(unsigned*)&g_ah[(size_t)row * D + col] = hh;
        *(unsigned*)&g_al[(size_t)row * D + col] = ll;
        split_pair(co[nt][2] * inv1, co[nt][3] * inv1, hh, ll);
        *(unsigned*)&g_ah[(size_t)(row + 8) * D + col] = hh;
        *(unsigned*)&g_al[(size_t)(row + 8) * D + col] = ll;
    }
}

// ---------------------------------------------------------------------------
// kernel_launch
// ---------------------------------------------------------------------------
extern "C" void kernel_launch(void* const* d_in, const int* in_sizes, int n_in,
                              void* d_out, int out_size) {
    const float* x  = (const float*)d_in[0];
    const float* WQ = (const float*)d_in[1];
    const float* WK = (const float*)d_in[2];
    const float* WV = (const float*)d_in[3];
    const float* WO = (const float*)d_in[4];
    float* out = (float*)d_out;

    conv_x_kernel<<<(S * D) / (256 * 4), 256>>>(x);
    conv_w_kernel<<<(4 * D * D) / (256 * 4), 256>>>(WQ, WK, WV, WO);

    dim3 gq(D / 64, S / 128, 3);
    proj_gemm_kernel<<<gq, 256>>>();

    dim3 ga(S / 64, H);
    attn_kernel<<<ga, 128>>>();

    dim3 go(D / 64, S / 128);
    out_gemm_kernel<<<go, 256>>>(out);
}

// round 4
// speedup vs baseline: 4.0853x; 1.0020x over previous
#include <cuda_runtime.h>
#include <cuda_bf16.h>

#define S 4096
#define D 1024
#define H 16

// ---------------------------------------------------------------------------
// Device-global scratch. All fp32 tensors stored as split bf16 (hi + lo);
// 3x bf16 MMA (hi*hi + hi*lo + lo*hi) recovers ~17 mantissa bits.
// ---------------------------------------------------------------------------
__device__ __nv_bfloat16 g_xh[S * D], g_xl[S * D];
__device__ __nv_bfloat16 g_wh[3][D * D], g_wl[3][D * D];
__device__ __nv_bfloat16 g_woh[D * D], g_wol[D * D];
__device__ __nv_bfloat16 g_qh[S * D], g_ql[S * D];
__device__ __nv_bfloat16 g_kh[S * D], g_kl[S * D];
__device__ __nv_bfloat16 g_vh[S * D], g_vl[S * D];
__device__ __nv_bfloat16 g_ah[S * D], g_al[S * D];

// ---------------------------------------------------------------------------
// Helpers
// ---------------------------------------------------------------------------
__device__ __forceinline__ unsigned smem_u32(const void* p) {
    return (unsigned)__cvta_generic_to_shared(p);
}

__device__ __forceinline__ void split_pair(float f0, float f1,
                                           unsigned& h, unsigned& l) {
    __nv_bfloat162 hh = __floats2bfloat162_rn(f0, f1);
    float r0 = f0 - __bfloat162float(hh.x);
    float r1 = f1 - __bfloat162float(hh.y);
    __nv_bfloat162 ll = __floats2bfloat162_rn(r0, r1);
    h = *reinterpret_cast<unsigned*>(&hh);
    l = *reinterpret_cast<unsigned*>(&ll);
}

__device__ __forceinline__ void ldm_x4(unsigned addr, unsigned& r0, unsigned& r1,
                                       unsigned& r2, unsigned& r3) {
    asm volatile("ldmatrix.sync.aligned.m8n8.x4.shared.b16 {%0,%1,%2,%3},[%4];\n"
                 : "=r"(r0), "=r"(r1), "=r"(r2), "=r"(r3) : "r"(addr));
}

__device__ __forceinline__ void ldm_x4_t(unsigned addr, unsigned& r0, unsigned& r1,
                                         unsigned& r2, unsigned& r3) {
    asm volatile("ldmatrix.sync.aligned.m8n8.x4.trans.shared.b16 {%0,%1,%2,%3},[%4];\n"
                 : "=r"(r0), "=r"(r1), "=r"(r2), "=r"(r3) : "r"(addr));
}

__device__ __forceinline__ void mma_bf16(float c[4], const unsigned a[4],
                                         const unsigned b[2]) {
    asm volatile(
        "mma.sync.aligned.m16n8k16.row.col.f32.bf16.bf16.f32 "
        "{%0,%1,%2,%3},{%4,%5,%6,%7},{%8,%9},{%0,%1,%2,%3};\n"
        : "+f"(c[0]), "+f"(c[1]), "+f"(c[2]), "+f"(c[3])
        : "r"(a[0]), "r"(a[1]), "r"(a[2]), "r"(a[3]), "r"(b[0]), "r"(b[1]));
}

__device__ __forceinline__ void cp16(uint4* dst_smem, const void* src) {
    unsigned d = smem_u32(dst_smem);
    asm volatile("cp.async.cg.shared.global [%0],[%1],16;\n" :: "r"(d), "l"(src));
}
#define CP_COMMIT() asm volatile("cp.async.commit_group;\n" ::: "memory")
#define CP_WAIT1()  asm volatile("cp.async.wait_group 1;\n" ::: "memory")

// ---------------------------------------------------------------------------
// Conversion kernels: fp32 -> (bf16 hi, bf16 lo)
// ---------------------------------------------------------------------------
__global__ __launch_bounds__(256) void conv_x_kernel(const float* __restrict__ x) {
    int i = (blockIdx.x * 256 + threadIdx.x) * 4;
    float4 v = *(const float4*)(x + i);
    unsigned h0, l0, h1, l1;
    split_pair(v.x, v.y, h0, l0);
    split_pair(v.z, v.w, h1, l1);
    ((unsigned*)g_xh)[(i >> 1) + 0] = h0; ((unsigned*)g_xh)[(i >> 1) + 1] = h1;
    ((unsigned*)g_xl)[(i >> 1) + 0] = l0; ((unsigned*)g_xl)[(i >> 1) + 1] = l1;
}

__global__ __launch_bounds__(256) void conv_w_kernel(const float* __restrict__ WQ,
                                                     const float* __restrict__ WK,
                                                     const float* __restrict__ WV,
                                                     const float* __restrict__ WO) {
    int i = (blockIdx.x * 256 + threadIdx.x) * 4;
    int m = i >> 20;
    int off = i & ((D * D) - 1);
    const float* W = (m == 0) ? WQ : (m == 1) ? WK : (m == 2) ? WV : WO;
    __nv_bfloat16* dh = (m == 3) ? g_woh : g_wh[m];
    __nv_bfloat16* dl = (m == 3) ? g_wol : g_wl[m];
    float4 v = *(const float4*)(W + off);
    unsigned h0, l0, h1, l1;
    split_pair(v.x, v.y, h0, l0);
    split_pair(v.z, v.w, h1, l1);
    ((unsigned*)dh)[(off >> 1) + 0] = h0; ((unsigned*)dh)[(off >> 1) + 1] = h1;
    ((unsigned*)dl)[(off >> 1) + 0] = l0; ((unsigned*)dl)[(off >> 1) + 1] = l1;
}

// ---------------------------------------------------------------------------
// GEMM core: C[128x64] = A[128xK] * B[64xK]^T, split-bf16 x3 MMA.
// 256 threads = 8 warps as 4(m) x 2(n); warp tile 32x32.
// K-step 32, cp.async double-buffered (2 x 24KB stages = 48KB).
// ---------------------------------------------------------------------------
__device__ __forceinline__ void gemm_core(const __nv_bfloat16* __restrict__ Ah,
                                          const __nv_bfloat16* __restrict__ Al,
                                          const __nv_bfloat16* __restrict__ Bh,
                                          const __nv_bfloat16* __restrict__ Bl,
                                          int bm, int bn, float (&c)[2][4][4]) {
    __shared__ uint4 sm[3072];   // 48 KB
    const int tid = threadIdx.x;
    const int wid = tid >> 5, lane = tid & 31;
    const int wm = wid >> 1, wn = wid & 1;
    const int lr = (lane & 7) + ((lane >> 3) & 1) * 8;
    const int lc = lane >> 4;
    const unsigned sb = smem_u32(sm);

#pragma unroll
    for (int mt = 0; mt < 2; mt++)
#pragma unroll
        for (int nt = 0; nt < 4; nt++)
#pragma unroll
            for (int j = 0; j < 4; j++) c[mt][nt][j] = 0.0f;

    auto issue = [&](int ks, int s) {
        const int base = s * 1536;
#pragma unroll
        for (int t = 0; t < 2; t++) {
            int q = tid * 2 + t;
            int r = q >> 2, cc = q & 3;
            int sw = r * 4 + (cc ^ ((r >> 1) & 3));
            size_t g = (size_t)(bm + r) * D + ks * 32 + cc * 8;
            cp16(&sm[base + sw], Ah + g);
            cp16(&sm[base + 512 + sw], Al + g);
        }
        {
            int r = tid >> 2, cc = tid & 3;
            int sw = r * 4 + (cc ^ ((r >> 1) & 3));
            size_t g = (size_t)(bn + r) * D + ks * 32 + cc * 8;
            cp16(&sm[base + 1024 + sw], Bh + g);
            cp16(&sm[base + 1280 + sw], Bl + g);
        }
    };

    issue(0, 0); CP_COMMIT();
    issue(1, 1); CP_COMMIT();

    for (int i = 0; i < D / 32; i++) {
        CP_WAIT1();
        __syncthreads();
        const unsigned base = sb + (i & 1) * 24576;
#pragma unroll
        for (int kk = 0; kk < 2; kk++) {
            unsigned ah[2][4], al[2][4], bh[4][2], bl[4][2];
#pragma unroll
            for (int mt = 0; mt < 2; mt++) {
                int row = wm * 32 + mt * 16 + lr;
                int off = (row * 4 + (((kk * 2) + lc) ^ ((row >> 1) & 3))) * 16;
                ldm_x4(base + off, ah[mt][0], ah[mt][1], ah[mt][2], ah[mt][3]);
                ldm_x4(base + 8192 + off, al[mt][0], al[mt][1], al[mt][2], al[mt][3]);
            }
#pragma unroll
            for (int np = 0; np < 2; np++) {
                int rown = wn * 32 + np * 16 + lr;
                int off = (rown * 4 + (((kk * 2) + lc) ^ ((rown >> 1) & 3))) * 16;
                unsigned t0, t1, t2, t3;
                ldm_x4(base + 16384 + off, t0, t1, t2, t3);
                bh[2 * np][0] = t0; bh[2 * np][1] = t2;
                bh[2 * np + 1][0] = t1; bh[2 * np + 1][1] = t3;
                ldm_x4(base + 20480 + off, t0, t1, t2, t3);
                bl[2 * np][0] = t0; bl[2 * np][1] = t2;
                bl[2 * np + 1][0] = t1; bl[2 * np + 1][1] = t3;
            }
#pragma unroll
            for (int mt = 0; mt < 2; mt++)
#pragma unroll
                for (int nt = 0; nt < 4; nt++) {
                    mma_bf16(c[mt][nt], ah[mt], bh[nt]);
                    mma_bf16(c[mt][nt], ah[mt], bl[nt]);
                    mma_bf16(c[mt][nt], al[mt], bh[nt]);
                }
        }
        __syncthreads();
        if (i + 2 < D / 32) issue(i + 2, i & 1);
        CP_COMMIT();
    }
}

// Projections: Q/K/V = x @ W^T; Q scaled by (1/8)*log2(e) for base-2 softmax.
__global__ __launch_bounds__(256) void proj_gemm_kernel() {
    const int z = blockIdx.z;
    const int bm = blockIdx.y * 128, bn = blockIdx.x * 64;
    float c[2][4][4];
    gemm_core(g_xh, g_xl, g_wh[z], g_wl[z], bm, bn, c);

    __nv_bfloat16* Ch = (z == 0) ? g_qh : (z == 1) ? g_kh : g_vh;
    __nv_bfloat16* Cl = (z == 0) ? g_ql : (z == 1) ? g_kl : g_vl;
    const float scale = (z == 0) ? 0.18033688f : 1.0f;   // 0.125 * log2(e)

    const int wid = threadIdx.x >> 5, lane = threadIdx.x & 31;
    const int wm = wid >> 1, wn = wid & 1;
#pragma unroll
    for (int mt = 0; mt < 2; mt++)
#pragma unroll
        for (int nt = 0; nt < 4; nt++) {
            int row = bm + wm * 32 + mt * 16 + (lane >> 2);
            int col = bn + wn * 32 + nt * 8 + (lane & 3) * 2;
            unsigned h, l;
            split_pair(c[mt][nt][0] * scale, c[mt][nt][1] * scale, h, l);
            *(unsigned*)&Ch[(size_t)row * D + col] = h;
            *(unsigned*)&Cl[(size_t)row * D + col] = l;
            split_pair(c[mt][nt][2] * scale, c[mt][nt][3] * scale, h, l);
            *(unsigned*)&Ch[(size_t)(row + 8) * D + col] = h;
            *(unsigned*)&Cl[(size_t)(row + 8) * D + col] = l;
        }
}

// Output projection: out = A @ W_O^T (fp32)
__global__ __launch_bounds__(256) void out_gemm_kernel(float* __restrict__ out) {
    const int bm = blockIdx.y * 128, bn = blockIdx.x * 64;
    float c[2][4][4];
    gemm_core(g_ah, g_al, g_woh, g_wol, bm, bn, c);

    const int wid = threadIdx.x >> 5, lane = threadIdx.x & 31;
    const int wm = wid >> 1, wn = wid & 1;
#pragma unroll
    for (int mt = 0; mt < 2; mt++)
#pragma unroll
        for (int nt = 0; nt < 4; nt++) {
            int row = bm + wm * 32 + mt * 16 + (lane >> 2);
            int col = bn + wn * 32 + nt * 8 + (lane & 3) * 2;
            float2 v0 = {c[mt][nt][0], c[mt][nt][1]};
            float2 v1 = {c[mt][nt][2], c[mt][nt][3]};
            *(float2*)&out[(size_t)row * D + col] = v0;
            *(float2*)&out[(size_t)(row + 8) * D + col] = v1;
        }
}

// ---------------------------------------------------------------------------
// Flash attention: 128-thread CTA = 4 warps = 64 q rows, 4 CTAs/SM.
// 32-key tiles, cp.async double-buffered KV. Q (hi/lo) staged in SMEM and
// re-read per kd via ldmatrix (saves 32 regs -> occupancy 4).
// SMEM (uint4 idx): KVs0 [0,1024) KVs1 [1024,2048) Qh [2048,2560) Ql [2560,3072)
//   each KV stage: Khi[0,256) Klo[256,512) Vhi[512,768) Vlo[768,1024)
// Base-2 softmax: Q pre-scaled by 0.125*log2(e), p = exp2(s - m).
// ---------------------------------------------------------------------------
__global__ __launch_bounds__(128, 4) void attn_kernel() {
    __shared__ uint4 sm[3072];   // 48 KB

    const int tid = threadIdx.x, wid = tid >> 5, lane = tid & 31;
    const int h = blockIdx.y;
    const int qb = blockIdx.x * 64;
    const unsigned sb = smem_u32(sm);
    const int lr = (lane & 7) + ((lane >> 3) & 1) * 8;
    const int lc = lane >> 4;

    // ---- stage Q (hi/lo) via cp.async ----
#pragma unroll
    for (int t = 0; t < 4; t++) {
        int idx = tid + t * 128;
        int row = idx >> 3, cc = idx & 7;
        int sw = row * 8 + (cc ^ (row & 7));
        size_t g = (size_t)(qb + row) * D + h * 64 + cc * 8;
        cp16(&sm[2048 + sw], g_qh + g);
        cp16(&sm[2560 + sw], g_ql + g);
    }
    CP_COMMIT();

    auto issue = [&](int kt, int s) {
        const int base = s * 1024;
#pragma unroll
        for (int t = 0; t < 2; t++) {
            int q = tid * 2 + t;
            int rr = q >> 3, cc = q & 7;
            int sw = rr * 8 + (cc ^ (rr & 7));
            size_t g = (size_t)(kt * 32 + rr) * D + h * 64 + cc * 8;
            cp16(&sm[base + sw], g_kh + g);
            cp16(&sm[base + 256 + sw], g_kl + g);
            cp16(&sm[base + 512 + sw], g_vh + g);
            cp16(&sm[base + 768 + sw], g_vl + g);
        }
    };

    issue(0, 0); CP_COMMIT();
    issue(1, 1); CP_COMMIT();

    float co[8][4];
#pragma unroll
    for (int nt = 0; nt < 8; nt++)
#pragma unroll
        for (int j = 0; j < 4; j++) co[nt][j] = 0.0f;
    float m0 = -1e30f, m1 = -1e30f, l0 = 0.0f, l1 = 0.0f;

    const int qrow = wid * 16 + lr;

    for (int kt = 0; kt < S / 32; kt++) {
        CP_WAIT1();
        __syncthreads();
        const unsigned base = sb + (kt & 1) * 16384;

        // ---- scores: 16 x 32 per warp ----
        float sc[4][4];
#pragma unroll
        for (int nt = 0; nt < 4; nt++)
#pragma unroll
            for (int j = 0; j < 4; j++) sc[nt][j] = 0.0f;

#pragma unroll
        for (int kd = 0; kd < 4; kd++) {
            unsigned qh[4], ql[4];
            int qoff = (qrow * 8 + (((kd * 2) + lc) ^ (qrow & 7))) * 16;
            ldm_x4(sb + 32768 + qoff, qh[0], qh[1], qh[2], qh[3]);
            ldm_x4(sb + 40960 + qoff, ql[0], ql[1], ql[2], ql[3]);
#pragma unroll
            for (int np = 0; np < 2; np++) {
                int rown = np * 16 + lr;
                int off = (rown * 8 + (((kd * 2) + lc) ^ (rown & 7))) * 16;
                unsigned t0, t1, t2, t3, u0, u1, u2, u3;
                ldm_x4(base + off, t0, t1, t2, t3);          // K hi
                ldm_x4(base + 4096 + off, u0, u1, u2, u3);   // K lo
                unsigned bh0[2] = {t0, t2}, bh1[2] = {t1, t3};
                unsigned bl0[2] = {u0, u2}, bl1[2] = {u1, u3};
                mma_bf16(sc[2 * np], qh, bh0);
                mma_bf16(sc[2 * np], qh, bl0);
                mma_bf16(sc[2 * np], ql, bh0);
                mma_bf16(sc[2 * np + 1], qh, bh1);
                mma_bf16(sc[2 * np + 1], qh, bl1);
                mma_bf16(sc[2 * np + 1], ql, bh1);
            }
        }

        // ---- online softmax (base 2) ----
        float tm0 = -1e30f, tm1 = -1e30f;
#pragma unroll
        for (int t = 0; t < 4; t++) {
            tm0 = fmaxf(tm0, fmaxf(sc[t][0], sc[t][1]));
            tm1 = fmaxf(tm1, fmaxf(sc[t][2], sc[t][3]));
        }
        tm0 = fmaxf(tm0, __shfl_xor_sync(0xffffffffu, tm0, 1));
        tm0 = fmaxf(tm0, __shfl_xor_sync(0xffffffffu, tm0, 2));
        tm1 = fmaxf(tm1, __shfl_xor_sync(0xffffffffu, tm1, 1));
        tm1 = fmaxf(tm1, __shfl_xor_sync(0xffffffffu, tm1, 2));
        float mn0 = fmaxf(m0, tm0), mn1 = fmaxf(m1, tm1);
        float corr0 = exp2f(m0 - mn0), corr1 = exp2f(m1 - mn1);
        m0 = mn0; m1 = mn1;
        float ps0 = 0.0f, ps1 = 0.0f;
#pragma unroll
        for (int t = 0; t < 4; t++) {
            sc[t][0] = exp2f(sc[t][0] - m0); ps0 += sc[t][0];
            sc[t][1] = exp2f(sc[t][1] - m0); ps0 += sc[t][1];
            sc[t][2] = exp2f(sc[t][2] - m1); ps1 += sc[t][2];
            sc[t][3] = exp2f(sc[t][3] - m1); ps1 += sc[t][3];
        }
        l0 = l0 * corr0 + ps0;
        l1 = l1 * corr1 + ps1;
#pragma unroll
        for (int nt = 0; nt < 8; nt++) {
            co[nt][0] *= corr0; co[nt][1] *= corr0;
            co[nt][2] *= corr1; co[nt][3] *= corr1;
        }

        // ---- O += P * V ----
#pragma unroll
        for (int u = 0; u < 2; u++) {
            unsigned pah[4], pal[4];
            split_pair(sc[2 * u][0], sc[2 * u][1], pah[0], pal[0]);
            split_pair(sc[2 * u][2], sc[2 * u][3], pah[1], pal[1]);
            split_pair(sc[2 * u + 1][0], sc[2 * u + 1][1], pah[2], pal[2]);
            split_pair(sc[2 * u + 1][2], sc[2 * u + 1][3], pah[3], pal[3]);
#pragma unroll
            for (int jp = 0; jp < 4; jp++) {
                int rowv = u * 16 + lr;
                int off = (rowv * 8 + (((jp * 2) + lc) ^ (rowv & 7))) * 16;
                unsigned t0, t1, t2, t3, u0, u1, u2, u3;
                ldm_x4_t(base + 8192 + off, t0, t1, t2, t3);    // V hi
                ldm_x4_t(base + 12288 + off, u0, u1, u2, u3);   // V lo
                unsigned vh0[2] = {t0, t1}, vh1[2] = {t2, t3};
                unsigned vl0[2] = {u0, u1}, vl1[2] = {u2, u3};
                mma_bf16(co[2 * jp], pah, vh0);
                mma_bf16(co[2 * jp], pah, vl0);
                mma_bf16(co[2 * jp], pal, vh0);
                mma_bf16(co[2 * jp + 1], pah, vh1);
                mma_bf16(co[2 * jp + 1], pah, vl1);
                mma_bf16(co[2 * jp + 1], pal, vh1);
            }
        }
        __syncthreads();
        if (kt + 2 < S / 32) issue(kt + 2, kt & 1);
        CP_COMMIT();
    }

    // ---- finalize ----
    l0 += __shfl_xor_sync(0xffffffffu, l0, 1);
    l0 += __shfl_xor_sync(0xffffffffu, l0, 2);
    l1 += __shfl_xor_sync(0xffffffffu, l1, 1);
    l1 += __shfl_xor_sync(0xffffffffu, l1, 2);
    float inv0 = 1.0f / l0, inv1 = 1.0f / l1;

    int row = qb + wid * 16 + (lane >> 2);
#pragma unroll
    for (int nt = 0; nt < 8; nt++) {
        int col = h * 64 + nt * 8 + (lane & 3) * 2;
        unsigned hh, ll;
        split_pair(co[nt][0] * inv0, co[nt][1] * inv0, hh, ll);
        *(unsigned*)&g_ah[(size_t)row * D + col] = hh;
        *(unsigned*)&g_al[(size_t)row * D + col] = ll;
        split_pair(co[nt][2] * inv1, co[nt][3] * inv1, hh, ll);
        *(unsigned*)&g_ah[(size_t)(row + 8) * D + col] = hh;
        *(unsigned*)&g_al[(size_t)(row + 8) * D + col] = ll;
    }
}

// ---------------------------------------------------------------------------
// kernel_launch
// ---------------------------------------------------------------------------
extern "C" void kernel_launch(void* const* d_in, const int* in_sizes, int n_in,
                              void* d_out, int out_size) {
    const float* x  = (const float*)d_in[0];
    const float* WQ = (const float*)d_in[1];
    const float* WK = (const float*)d_in[2];
    const float* WV = (const float*)d_in[3];
    const float* WO = (const float*)d_in[4];
    float* out = (float*)d_out;

    conv_x_kernel<<<(S * D) / (256 * 4), 256>>>(x);
    conv_w_kernel<<<(4 * D * D) / (256 * 4), 256>>>(WQ, WK, WV, WO);

    dim3 gq(D / 64, S / 128, 3);
    proj_gemm_kernel<<<gq, 256>>>();

    dim3 ga(S / 64, H);
    attn_kernel<<<ga, 128>>>();

    dim3 go(D / 64, S / 128);
    out_gemm_kernel<<<go, 256>>>(out);
}